// round 8
// baseline (speedup 1.0000x reference)
#include <cuda_runtime.h>
#include <stdint.h>

#define N_   32
#define H_   56
#define W_   56
#define C_   256
#define HP   58          /* padded height */
#define WP   58          /* padded width (logical) */
#define WPS  64          /* padded row stride in words (aligned) */
#define COUT 256
#define NTAP 9
#define NWRD 72          /* 9 taps * 8 cin-groups */
#define NXP  (N_ * HP * WPS)        /* words per bit-plane = 118784 */
#define NTILES (N_ * H_ * 7)        /* 8-pixel tiles = 12544 */
#define NGRP  (NTILES / 8)          /* warp-groups of 8 tiles = 1568 */

// Scratch (device globals — no allocation allowed)
__device__ uint32_t g_kbits[NWRD * COUT];
__device__ float    g_kpart[NWRD * COUT];
__device__ float    g_alpha[COUT];
__device__ uint32_t g_xbt [8 * NXP];        // planar packed x sign bits
__device__ float    g_betap[NXP];           // sum |x| per padded pixel

__device__ __forceinline__ uint32_t xor3(uint32_t a, uint32_t b, uint32_t c) {
    return a ^ b ^ c;
}
__device__ __forceinline__ uint32_t maj3(uint32_t a, uint32_t b, uint32_t c) {
    return (a & b) | (a & c) | (b & c);
}

// ---------------------------------------------------------------------------
__global__ void prep_k1(const float* __restrict__ k) {
    int w  = blockIdx.x;        // 0..71
    int co = threadIdx.x;       // 0..255
    const float* base = k + (size_t)w * 32 * COUT + co;
    uint32_t bits = 0;
    float s = 0.f;
#pragma unroll
    for (int b = 0; b < 32; b++) {
        float v = base[(size_t)b * COUT];
        if (v > 0.f) bits |= (1u << b);
        s += fabsf(v);
    }
    g_kbits[w * COUT + co] = bits;
    g_kpart[w * COUT + co] = s;
}

__global__ void prep_k2() {
    int co = threadIdx.x;
    float s = 0.f;
#pragma unroll
    for (int w = 0; w < NWRD; w++) s += g_kpart[w * COUT + co];
    g_alpha[co] = s * (1.f / (NTAP * C_));
}

// ---------------------------------------------------------------------------
__global__ void prep_x(const float* __restrict__ x) {
    int pix  = blockIdx.x * 8 + (threadIdx.x >> 5);
    int lane = threadIdx.x & 31;
    if (pix >= N_ * HP * WP) return;
    int n  = pix / (HP * WP);
    int r  = pix % (HP * WP);
    int hp = r / WP, wp = r % WP;
    int ppos = (n * HP + hp) * WPS + wp;
    if (hp >= 1 && hp <= H_ && wp >= 1 && wp <= W_) {
        const float* xp = x + (((size_t)n * H_ + (hp - 1)) * W_ + (wp - 1)) * C_;
        float asum = 0.f;
        uint32_t bm[8];
#pragma unroll
        for (int j = 0; j < 8; j++) {
            float v = xp[j * 32 + lane];
            bm[j] = __ballot_sync(0xffffffffu, v > 0.f);
            asum += fabsf(v);
        }
#pragma unroll
        for (int o = 16; o; o >>= 1) asum += __shfl_xor_sync(0xffffffffu, asum, o);
#pragma unroll
        for (int j = 0; j < 8; j++)
            if (lane == j) g_xbt[(size_t)j * NXP + ppos] = bm[j];
        if (lane == 0) g_betap[ppos] = asum;
    } else {
        if (lane < 8) g_xbt[(size_t)lane * NXP + ppos] = 0u;
        if (lane == 0) g_betap[ppos] = 0.f;
    }
}

// ---------------------------------------------------------------------------
// Main conv: full 9-input CSA compressor, 8-pixel warp tiles.
// Warp = 8 output pixels x 64 couts (2 per lane). blockIdx.y = cout-group.
// Accumulator: one reg per (pixel,cout): S | w2<<10 | w4<<20.
__global__ void __launch_bounds__(256, 2) binconv_main(
        const float* __restrict__ bias, float* __restrict__ out) {
    extern __shared__ uint32_t s_k[];   // NWRD * 64 words = 18KB slice

    const int cg = blockIdx.y;
    {
        const uint4* src = (const uint4*)g_kbits;
        uint4*       dst = (uint4*)s_k;
        for (int m = threadIdx.x; m < NWRD * 16; m += 256) {
            int w = m >> 4, j = m & 15;
            dst[m] = src[w * 64 + cg * 16 + j];
        }
    }
    __syncthreads();

    const int warp = threadIdx.x >> 5;
    const int lane = threadIdx.x & 31;
    const int co0  = cg * 64 + 2 * lane;

    const float2 al = *(const float2*)(g_alpha + co0);
    const float2 bi = *(const float2*)(bias + co0);

    for (int grp = blockIdx.x; grp < NGRP; grp += gridDim.x) {
        int t  = grp * 8 + warp;
        int tw = t % 7;
        int tr = t / 7;
        int th = tr % H_;
        int n  = tr / H_;
        int rb = (n * HP + th) * WPS + tw * 8;

        uint32_t acc0[8] = {0,0,0,0,0,0,0,0};   // cout co0
        uint32_t acc1[8] = {0,0,0,0,0,0,0,0};   // cout co0+1

#pragma unroll 1
        for (int gc = 0; gc < 8; gc++) {
            const uint32_t* xplane = g_xbt + (size_t)gc * NXP + rb;
            // 3 rows x 10 words, loaded once
            uint32_t r0[10], r1[10], r2[10];
            {
                uint4 a = *(const uint4*)(xplane);
                uint4 b = *(const uint4*)(xplane + 4);
                uint2 c = *(const uint2*)(xplane + 8);
                r0[0]=a.x; r0[1]=a.y; r0[2]=a.z; r0[3]=a.w;
                r0[4]=b.x; r0[5]=b.y; r0[6]=b.z; r0[7]=b.w;
                r0[8]=c.x; r0[9]=c.y;
            }
            {
                uint4 a = *(const uint4*)(xplane + WPS);
                uint4 b = *(const uint4*)(xplane + WPS + 4);
                uint2 c = *(const uint2*)(xplane + WPS + 8);
                r1[0]=a.x; r1[1]=a.y; r1[2]=a.z; r1[3]=a.w;
                r1[4]=b.x; r1[5]=b.y; r1[6]=b.z; r1[7]=b.w;
                r1[8]=c.x; r1[9]=c.y;
            }
            {
                uint4 a = *(const uint4*)(xplane + 2 * WPS);
                uint4 b = *(const uint4*)(xplane + 2 * WPS + 4);
                uint2 c = *(const uint2*)(xplane + 2 * WPS + 8);
                r2[0]=a.x; r2[1]=a.y; r2[2]=a.z; r2[3]=a.w;
                r2[4]=b.x; r2[5]=b.y; r2[6]=b.z; r2[7]=b.w;
                r2[8]=c.x; r2[9]=c.y;
            }
            uint2 kv[9];
#pragma unroll
            for (int tap = 0; tap < 9; tap++)
                kv[tap] = *(const uint2*)(s_k + (tap * 8 + gc) * 64 + 2 * lane);

#pragma unroll
            for (int p = 0; p < 8; p++) {
                {   // cout co0
                    uint32_t u0 = r0[p] ^ kv[0].x, u1 = r0[p+1] ^ kv[1].x, u2 = r0[p+2] ^ kv[2].x;
                    uint32_t u3 = r1[p] ^ kv[3].x, u4 = r1[p+1] ^ kv[4].x, u5 = r1[p+2] ^ kv[5].x;
                    uint32_t u6 = r2[p] ^ kv[6].x, u7 = r2[p+1] ^ kv[7].x, u8 = r2[p+2] ^ kv[8].x;
                    uint32_t s0 = xor3(u0,u1,u2), c0 = maj3(u0,u1,u2);
                    uint32_t s1 = xor3(u3,u4,u5), c1 = maj3(u3,u4,u5);
                    uint32_t s2 = xor3(u6,u7,u8), c2 = maj3(u6,u7,u8);
                    uint32_t S  = xor3(s0,s1,s2), c3 = maj3(s0,s1,s2);
                    uint32_t s4 = xor3(c0,c1,c2), c4 = maj3(c0,c1,c2);
                    uint32_t w2 = (uint32_t)__popc(c3) + (uint32_t)__popc(s4);
                    acc0[p] += (uint32_t)__popc(S) + (w2 << 10)
                             + ((uint32_t)__popc(c4) << 20);
                }
                {   // cout co0+1
                    uint32_t u0 = r0[p] ^ kv[0].y, u1 = r0[p+1] ^ kv[1].y, u2 = r0[p+2] ^ kv[2].y;
                    uint32_t u3 = r1[p] ^ kv[3].y, u4 = r1[p+1] ^ kv[4].y, u5 = r1[p+2] ^ kv[5].y;
                    uint32_t u6 = r2[p] ^ kv[6].y, u7 = r2[p+1] ^ kv[7].y, u8 = r2[p+2] ^ kv[8].y;
                    uint32_t s0 = xor3(u0,u1,u2), c0 = maj3(u0,u1,u2);
                    uint32_t s1 = xor3(u3,u4,u5), c1 = maj3(u3,u4,u5);
                    uint32_t s2 = xor3(u6,u7,u8), c2 = maj3(u6,u7,u8);
                    uint32_t S  = xor3(s0,s1,s2), c3 = maj3(s0,s1,s2);
                    uint32_t s4 = xor3(c0,c1,c2), c4 = maj3(c0,c1,c2);
                    uint32_t w2 = (uint32_t)__popc(c3) + (uint32_t)__popc(s4);
                    acc1[p] += (uint32_t)__popc(S) + (w2 << 10)
                             + ((uint32_t)__popc(c4) << 20);
                }
            }
        }

        // Epilogue: ksum[p] = 3x3 window sum of beta; out = dot*K*alpha + bias
        const float* bp = g_betap + rb;
        float rs[10];
        {
            float4 a = *(const float4*)(bp);
            float4 b = *(const float4*)(bp + WPS);
            float4 c = *(const float4*)(bp + 2 * WPS);
            rs[0] = a.x + b.x + c.x;  rs[1] = a.y + b.y + c.y;
            rs[2] = a.z + b.z + c.z;  rs[3] = a.w + b.w + c.w;
        }
        {
            float4 a = *(const float4*)(bp + 4);
            float4 b = *(const float4*)(bp + WPS + 4);
            float4 c = *(const float4*)(bp + 2 * WPS + 4);
            rs[4] = a.x + b.x + c.x;  rs[5] = a.y + b.y + c.y;
            rs[6] = a.z + b.z + c.z;  rs[7] = a.w + b.w + c.w;
        }
        {
            float2 a = *(const float2*)(bp + 8);
            float2 b = *(const float2*)(bp + WPS + 8);
            float2 c = *(const float2*)(bp + 2 * WPS + 8);
            rs[8] = a.x + b.x + c.x;  rs[9] = a.y + b.y + c.y;
        }

        float* op = out + (size_t)t * 8 * COUT + co0;
#pragma unroll
        for (int p = 0; p < 8; p++) {
            float ks = (rs[p] + rs[p + 1] + rs[p + 2]) * (1.f / 2304.f);
            uint32_t A0 = acc0[p], A1 = acc1[p];
            uint32_t T0 = (A0 & 1023u) + 2u * ((A0 >> 10) & 1023u) + 4u * (A0 >> 20);
            uint32_t T1 = (A1 & 1023u) + 2u * ((A1 >> 10) & 1023u) + 4u * (A1 >> 20);
            float d0 = 2304.f - 2.f * (float)T0;
            float d1 = 2304.f - 2.f * (float)T1;
            float2 o;
            o.x = d0 * (ks * al.x) + bi.x;
            o.y = d1 * (ks * al.y) + bi.y;
            *(float2*)(op + (size_t)p * COUT) = o;
        }
    }
}

// ---------------------------------------------------------------------------
extern "C" void kernel_launch(void* const* d_in, const int* in_sizes, int n_in,
                              void* d_out, int out_size) {
    (void)in_sizes; (void)n_in; (void)out_size;
    const float* x    = (const float*)d_in[0];
    const float* kern = (const float*)d_in[1];
    const float* bias = (const float*)d_in[2];
    float*       out  = (float*)d_out;

    prep_k1<<<NWRD, 256>>>(kern);
    prep_k2<<<1, 256>>>();

    const int npixp = N_ * HP * WP;
    prep_x<<<npixp / 8, 256>>>(x);

    const size_t smem_bytes = (size_t)NWRD * 64 * 4;   // 18432
    dim3 grid(74, 4);   // 296 blocks = 2 CTAs/SM resident
    binconv_main<<<grid, 256, smem_bytes>>>(bias, out);
}

// round 9
// speedup vs baseline: 1.5664x; 1.5664x over previous
#include <cuda_runtime.h>
#include <stdint.h>

#define N_   32
#define H_   56
#define W_   56
#define C_   256
#define HP   58          /* padded height */
#define WP   58          /* padded width (logical) */
#define WPS  64          /* padded row stride in words (aligned) */
#define COUT 256
#define NTAP 9
#define NWRD 72          /* 9 taps * 8 cin-groups */
#define NXP  (N_ * HP * WPS)        /* words per bit-plane = 118784 */
#define NTILES (N_ * H_ * 7)        /* 8-pixel tiles = 12544 */
#define NGRP  (NTILES / 8)          /* warp-groups of 8 tiles = 1568 */

// Scratch (device globals — no allocation allowed)
__device__ uint32_t g_kbits[NWRD * COUT];
__device__ float    g_kpart[NWRD * COUT];
__device__ float    g_alpha[COUT];
__device__ uint32_t g_xbt [8 * NXP];        // planar packed x sign bits
__device__ float    g_betap[NXP];           // sum |x| per padded pixel

// ---------------------------------------------------------------------------
__global__ void prep_k1(const float* __restrict__ k) {
    int w  = blockIdx.x;        // 0..71
    int co = threadIdx.x;       // 0..255
    const float* base = k + (size_t)w * 32 * COUT + co;
    uint32_t bits = 0;
    float s = 0.f;
#pragma unroll
    for (int b = 0; b < 32; b++) {
        float v = base[(size_t)b * COUT];
        if (v > 0.f) bits |= (1u << b);
        s += fabsf(v);
    }
    g_kbits[w * COUT + co] = bits;
    g_kpart[w * COUT + co] = s;
}

__global__ void prep_k2() {
    int co = threadIdx.x;
    float s = 0.f;
#pragma unroll
    for (int w = 0; w < NWRD; w++) s += g_kpart[w * COUT + co];
    g_alpha[co] = s * (1.f / (NTAP * C_));
}

// ---------------------------------------------------------------------------
__global__ void prep_x(const float* __restrict__ x) {
    int pix  = blockIdx.x * 8 + (threadIdx.x >> 5);
    int lane = threadIdx.x & 31;
    if (pix >= N_ * HP * WP) return;
    int n  = pix / (HP * WP);
    int r  = pix % (HP * WP);
    int hp = r / WP, wp = r % WP;
    int ppos = (n * HP + hp) * WPS + wp;
    if (hp >= 1 && hp <= H_ && wp >= 1 && wp <= W_) {
        const float* xp = x + (((size_t)n * H_ + (hp - 1)) * W_ + (wp - 1)) * C_;
        float asum = 0.f;
        uint32_t bm[8];
#pragma unroll
        for (int j = 0; j < 8; j++) {
            float v = xp[j * 32 + lane];
            bm[j] = __ballot_sync(0xffffffffu, v > 0.f);
            asum += fabsf(v);
        }
#pragma unroll
        for (int o = 16; o; o >>= 1) asum += __shfl_xor_sync(0xffffffffu, asum, o);
#pragma unroll
        for (int j = 0; j < 8; j++)
            if (lane == j) g_xbt[(size_t)j * NXP + ppos] = bm[j];
        if (lane == 0) g_betap[ppos] = asum;
    } else {
        if (lane < 8) g_xbt[(size_t)lane * NXP + ppos] = 0u;
        if (lane == 0) g_betap[ppos] = 0.f;
    }
}

// ---------------------------------------------------------------------------
// Main XNOR-popcount conv with kw-level carry-save adder (best measured body).
// popc(t0)+popc(t1)+popc(t2) = popc(t0^t1^t2) + 2*popc(maj(t0,t1,t2)).
// blockIdx.y = cout-group cg (64 couts). Warp = 8 pixels x 64 couts.
// R9 change: launch_bounds(256,5) -> <=51 regs so all 740 blocks are resident
// in ONE wave (5 CTAs/SM), eliminating R6's 25% ragged second wave.
__global__ void __launch_bounds__(256, 5) binconv_main(
        const float* __restrict__ bias, float* __restrict__ out) {
    extern __shared__ uint32_t s_k[];   // NWRD * 64 words = 18KB slice

    const int cg = blockIdx.y;
    {   // cooperative vectorized smem fill of this cg's slice
        const uint4* src = (const uint4*)g_kbits;
        uint4*       dst = (uint4*)s_k;
        for (int m = threadIdx.x; m < NWRD * 16; m += 256) {
            int w = m >> 4, j = m & 15;
            dst[m] = src[w * 64 + cg * 16 + j];
        }
    }
    __syncthreads();

    const int warp = threadIdx.x >> 5;
    const int lane = threadIdx.x & 31;
    const int co0  = cg * 64 + 2 * lane;

    const float2 al = *(const float2*)(g_alpha + co0);
    const float2 bi = *(const float2*)(bias + co0);

    for (int grp = blockIdx.x; grp < NGRP; grp += gridDim.x) {
        int t  = grp * 8 + warp;
        int tw = t % 7;
        int tr = t / 7;
        int th = tr % H_;
        int n  = tr / H_;
        int rb = (n * HP + th) * WPS + tw * 8;

        // packed 16-bit accumulators: lo16 = co0, hi16 = co0+1
        uint32_t accS[8] = {0,0,0,0,0,0,0,0};    // weight-1 popcounts (<= 768)
        uint32_t accM[8] = {0,0,0,0,0,0,0,0};    // weight-2 popcounts (<= 768)

#pragma unroll 2
        for (int gc = 0; gc < 8; gc++) {
            const uint32_t* xplane = g_xbt + (size_t)gc * NXP + rb;
#pragma unroll
            for (int kh = 0; kh < 3; kh++) {
                const uint4* xr = (const uint4*)(xplane + kh * WPS);
                uint4 q0 = xr[0], q1 = xr[1], q2 = xr[2];
                uint32_t xw[12] = {q0.x, q0.y, q0.z, q0.w,
                                   q1.x, q1.y, q1.z, q1.w,
                                   q2.x, q2.y, q2.z, q2.w};
                const uint2* k0 = (const uint2*)(s_k + ((kh * 3 + 0) * 8 + gc) * 64);
                const uint2* k1 = (const uint2*)(s_k + ((kh * 3 + 1) * 8 + gc) * 64);
                const uint2* k2 = (const uint2*)(s_k + ((kh * 3 + 2) * 8 + gc) * 64);
                uint2 kv0 = k0[lane], kv1 = k1[lane], kv2 = k2[lane];
#pragma unroll
                for (int p = 0; p < 8; p++) {
                    uint32_t t0 = xw[p] ^ kv0.x;
                    uint32_t t1 = xw[p + 1] ^ kv1.x;
                    uint32_t t2 = xw[p + 2] ^ kv2.x;
                    uint32_t s0 = t0 ^ t1 ^ t2;                      // LOP3 0x96
                    uint32_t m0 = (t0 & t1) | (t0 & t2) | (t1 & t2); // LOP3 0xE8
                    uint32_t u0 = xw[p] ^ kv0.y;
                    uint32_t u1 = xw[p + 1] ^ kv1.y;
                    uint32_t u2 = xw[p + 2] ^ kv2.y;
                    uint32_t s1 = u0 ^ u1 ^ u2;
                    uint32_t m1 = (u0 & u1) | (u0 & u2) | (u1 & u2);
                    accS[p] += (uint32_t)__popc(s0) + ((uint32_t)__popc(s1) << 16);
                    accM[p] += (uint32_t)__popc(m0) + ((uint32_t)__popc(m1) << 16);
                }
            }
        }

        // Epilogue: ksum[p] = 3x3 window sum of beta; out = dot*K*alpha + bias
        const float* bp = g_betap + rb;
        float rs[10];
        {
            float4 a = *(const float4*)(bp);
            float4 b = *(const float4*)(bp + WPS);
            float4 c = *(const float4*)(bp + 2 * WPS);
            rs[0] = a.x + b.x + c.x;  rs[1] = a.y + b.y + c.y;
            rs[2] = a.z + b.z + c.z;  rs[3] = a.w + b.w + c.w;
        }
        {
            float4 a = *(const float4*)(bp + 4);
            float4 b = *(const float4*)(bp + WPS + 4);
            float4 c = *(const float4*)(bp + 2 * WPS + 4);
            rs[4] = a.x + b.x + c.x;  rs[5] = a.y + b.y + c.y;
            rs[6] = a.z + b.z + c.z;  rs[7] = a.w + b.w + c.w;
        }
        {
            float2 a = *(const float2*)(bp + 8);
            float2 b = *(const float2*)(bp + WPS + 8);
            float2 c = *(const float2*)(bp + 2 * WPS + 8);
            rs[8] = a.x + b.x + c.x;  rs[9] = a.y + b.y + c.y;
        }

        float* op = out + (size_t)t * 8 * COUT + co0;
#pragma unroll
        for (int p = 0; p < 8; p++) {
            float ks = (rs[p] + rs[p + 1] + rs[p + 2]) * (1.f / 2304.f);
            uint32_t T0 = (accS[p] & 0xFFFFu) + 2u * (accM[p] & 0xFFFFu);
            uint32_t T1 = (accS[p] >> 16)     + 2u * (accM[p] >> 16);
            float d0 = 2304.f - 2.f * (float)T0;
            float d1 = 2304.f - 2.f * (float)T1;
            float2 o;
            o.x = d0 * (ks * al.x) + bi.x;
            o.y = d1 * (ks * al.y) + bi.y;
            *(float2*)(op + (size_t)p * COUT) = o;
        }
    }
}

// ---------------------------------------------------------------------------
extern "C" void kernel_launch(void* const* d_in, const int* in_sizes, int n_in,
                              void* d_out, int out_size) {
    (void)in_sizes; (void)n_in; (void)out_size;
    const float* x    = (const float*)d_in[0];
    const float* kern = (const float*)d_in[1];
    const float* bias = (const float*)d_in[2];
    float*       out  = (float*)d_out;

    prep_k1<<<NWRD, 256>>>(kern);
    prep_k2<<<1, 256>>>();

    const int npixp = N_ * HP * WP;
    prep_x<<<npixp / 8, 256>>>(x);

    const size_t smem_bytes = (size_t)NWRD * 64 * 4;   // 18432
    dim3 grid(185, 4);   // 740 blocks = 5 CTAs/SM resident -> single full wave
    binconv_main<<<grid, 256, smem_bytes>>>(bias, out);
}